// round 15
// baseline (speedup 1.0000x reference)
#include <cuda_runtime.h>
#include <cuda_bf16.h>
#include <cuda_fp16.h>
#include <cstdint>

// ---------------- problem constants ----------------
#define DIN   4096
#define DOUT  4096
#define MROWS 8192          // B*S = 4*2048
#define R0    32
#define R1    8
#define RTOT  40
#define NEXP  3
#define SCALING 0.5f        // 16/32

// ---------------- device scratch ----------------
__device__ __align__(256) float  g_sumw[DOUT * RTOT];   // masked coef sums  [O, 40]
__device__ __align__(256) float  g_fw  [DOUT * RTOT];   // fourier-transformed [O, 40]
__device__ __align__(256) __half g_wh[(size_t)DOUT * DIN];   // W_eff fp16
__device__ __align__(256) __half g_xh[(size_t)MROWS * DIN];  // x fp16
// statically zero-initialized; k_detect only ORs input-derived bits (idempotent)
__device__ unsigned int g_viol[2] = {0u, 0u};

// ---------------- helpers ----------------
__device__ __forceinline__ uint32_t smem_u32(const void* p) {
    uint32_t a;
    asm("{ .reg .u64 t; cvta.to.shared.u64 t, %1; cvt.u32.u64 %0, t; }" : "=r"(a) : "l"(p));
    return a;
}
#define SMEM_SWIZZLE_128B(off) ((off) ^ (((off) >> 3) & 0x70))

__device__ __forceinline__ void cp_async16(uint32_t saddr, const void* gaddr) {
    asm volatile("cp.async.cg.shared.global [%0], [%1], 16;" :: "r"(saddr), "l"(gaddr));
}
__device__ __forceinline__ void cp_commit() {
    asm volatile("cp.async.commit_group;" ::: "memory");
}
template <int N>
__device__ __forceinline__ void cp_wait() {
    asm volatile("cp.async.wait_group %0;" :: "n"(N) : "memory");
}

__device__ __forceinline__ void ldm_x4(uint32_t& r0, uint32_t& r1, uint32_t& r2, uint32_t& r3,
                                       uint32_t addr) {
    asm volatile("ldmatrix.sync.aligned.m8n8.x4.shared.b16 {%0,%1,%2,%3}, [%4];"
                 : "=r"(r0), "=r"(r1), "=r"(r2), "=r"(r3) : "r"(addr));
}

__device__ __forceinline__ void mma_f16(float& c0, float& c1, float& c2, float& c3,
                                        uint32_t a0, uint32_t a1, uint32_t a2, uint32_t a3,
                                        uint32_t b0, uint32_t b1) {
    asm volatile(
        "mma.sync.aligned.m16n8k16.row.col.f32.f16.f16.f32 "
        "{%0,%1,%2,%3}, {%4,%5,%6,%7}, {%8,%9}, {%0,%1,%2,%3};"
        : "+f"(c0), "+f"(c1), "+f"(c2), "+f"(c3)
        : "r"(a0), "r"(a1), "r"(a2), "r"(a3), "r"(b0), "r"(b1));
}

// ============================================================================
// Kernel 0: mask dtype detection (uint8 / int32 / float32 bools).
// ============================================================================
__global__ void k_detect(const unsigned int* __restrict__ w) {
    unsigned int v = w[blockIdx.x * blockDim.x + threadIdx.x];
    if (v > 1u) atomicOr(&g_viol[0], 1u);
    if (v != 0u && v != 0x3f800000u) atomicOr(&g_viol[1], 1u);
}

__device__ __forceinline__ bool mask_at(const void* m, int j, int mode) {
    if (mode == 1) return ((const int*)m)[j] != 0;
    if (mode == 2) return ((const float*)m)[j] != 0.f;
    return ((const unsigned char*)m)[j] != 0;
}

__device__ __forceinline__ float masked_sum(const float* c, const void* m,
                                            int o, int rr, int R, int mode) {
    float s = 0.f;
    #pragma unroll
    for (int e = 0; e < NEXP; ++e) {
        int j = e * DOUT * R + o * R + rr;
        s += mask_at(m, j, mode) ? c[j] : 0.f;
    }
    return s;
}

// ============================================================================
// Kernel 1 (FUSED): masked coefficient sums + DC/Nyquist init of g_fw.
// ============================================================================
__global__ void k_prep(const float* __restrict__ c0, const float* __restrict__ c1,
                       const void* __restrict__ m0, const void* __restrict__ m1) {
    int idx = blockIdx.x * blockDim.x + threadIdx.x;
    const int total = DOUT * RTOT;
    const int mode = (g_viol[0] == 0u) ? 1 : ((g_viol[1] == 0u) ? 2 : 0);
    if (idx < total) {
        int o = idx / RTOT, r = idx % RTOT;
        float s = (r < R0) ? masked_sum(c0, m0, o, r, R0, mode)
                           : masked_sum(c1, m1, o, r - R0, R1, mode);
        g_sumw[o * RTOT + r] = s;
    } else if (idx < 2 * total) {
        int j = idx - total;
        int t = j / RTOT, r = j % RTOT;
        float s0, sN;
        if (r < R0) {
            s0 = masked_sum(c0, m0, 0, r, R0, mode);
            sN = masked_sum(c0, m0, DOUT - 1, r, R0, mode);
        } else {
            s0 = masked_sum(c1, m1, 0, r - R0, R1, mode);
            sN = masked_sum(c1, m1, DOUT - 1, r - R0, R1, mode);
        }
        const float inv = 0.015625f;                   // 1/sqrt(4096)
        float sgn = (t & 1) ? -inv : inv;
        g_fw[j] = s0 * inv + sN * sgn;
    }
}

// ============================================================================
// Kernel 2: frequency-parallel Fourier accumulation with rotation recurrence.
// ============================================================================
__global__ void k_transform() {
    __shared__ float sc[128 * RTOT];       // 64 freqs (cos,sin rows) at a time
    int t = blockIdx.x * 128 + threadIdx.x;
    float acc[RTOT];
    #pragma unroll
    for (int r = 0; r < RTOT; ++r) acc[r] = 0.f;

    const float TWO_PI_OVER_N = 0.00153398078788564123f;
    float cd, sd;
    {
        int kt = t & 4095;
        int kt2 = (kt <= 2048) ? kt : (kt - 4096);
        __sincosf((float)kt2 * TWO_PI_OVER_N, &sd, &cd);
    }

    #pragma unroll
    for (int half = 0; half < 2; ++half) {
        int fs = 1 + blockIdx.y * 128 + half * 64;
        int nf = 2048 - fs; if (nf > 64) nf = 64;      // f max = 2047
        if (nf <= 0) break;
        int row0 = 2 * fs - 1;
        __syncthreads();
        for (int i = threadIdx.x; i < 2 * nf; i += 128) {
            const float4* src = (const float4*)(g_sumw + (size_t)(row0 + i) * RTOT);
            float4* dst = (float4*)(sc + i * RTOT);
            #pragma unroll
            for (int q = 0; q < 10; ++q) dst[q] = src[q];
        }
        __syncthreads();

        float cv, sv;
        {
            int k = (fs * t) & 4095;
            int k2 = (k <= 2048) ? k : (k - 4096);
            __sincosf((float)k2 * TWO_PI_OVER_N, &sv, &cv);
        }

        for (int j = 0; j < nf; ++j) {
            const float4* cc = (const float4*)(sc + (2 * j) * RTOT);
            const float4* ss = (const float4*)(sc + (2 * j + 1) * RTOT);
            #pragma unroll
            for (int q = 0; q < 10; ++q) {
                float4 a = cc[q]; float4 b = ss[q];
                acc[4*q+0] += a.x * cv + b.x * sv;
                acc[4*q+1] += a.y * cv + b.y * sv;
                acc[4*q+2] += a.z * cv + b.z * sv;
                acc[4*q+3] += a.w * cv + b.w * sv;
            }
            float ncv = cv * cd - sv * sd;
            sv = sv * cd + cv * sd;
            cv = ncv;
        }
    }
    const float s2 = 0.02209708691207961102f;          // sqrt(2/4096)
    float* dst = g_fw + (size_t)t * RTOT;
    #pragma unroll
    for (int r = 0; r < RTOT; ++r) atomicAdd(dst + r, acc[r] * s2);
}

// ============================================================================
// Kernel 3 (NEW, tensor-core): W_eff = W_base + (0.5*FW) @ enc, store fp16.
// GEMM with K=40 padded to 64: A = 0.5*FW [o,40] fp16, B[d][r] = enc[r][d].
// One K-chunk, same fragment layout as the main GEMM (128x128 tile, 8 warps
// of 64x32). DRAM-bound (~100MB) instead of FMA-bound (was 671M fp32 FMA).
// ============================================================================
__global__ __launch_bounds__(256) void k_build_w_mma(const float* __restrict__ Wb,
                                                     const float* __restrict__ enc0,
                                                     const float* __restrict__ enc1) {
    __shared__ __align__(1024) __half smA[128 * 64];   // 16 KB  (o x k, 128B rows)
    __shared__ __align__(1024) __half smB[128 * 64];   // 16 KB  (d x k)

    const int tid = threadIdx.x;
    const int wid = tid >> 5;
    const int lane = tid & 31;
    const int wm = wid & 1;          // 2 warps along M (o)
    const int wn = wid >> 1;         // 4 warps along N (d)
    const int o0 = blockIdx.y * 128; // gridDim.y = 32
    const int d0 = blockIdx.x * 128; // gridDim.x = 32

    const uint32_t sA = smem_u32(smA);
    const uint32_t sB = smem_u32(smB);

    // fill A: A[row][k] = (k<40) ? 0.5*g_fw[(o0+row)*40+k] : 0   (swizzled)
    // fill B: B[row][k] = enc[k][d0+row] (k<32: enc0, k<40: enc1-32, else 0)
    for (int i = tid; i < 128 * 64; i += 256) {
        const int row = i >> 6;
        const int k   = i & 63;
        const uint32_t off = SMEM_SWIZZLE_128B((uint32_t)(row * 128 + k * 2));
        float av = (k < RTOT) ? 0.5f * g_fw[(size_t)(o0 + row) * RTOT + k] : 0.f;
        float bv = 0.f;
        if (k < R0)        bv = enc0[(size_t)k * DIN + d0 + row];
        else if (k < RTOT) bv = enc1[(size_t)(k - R0) * DIN + d0 + row];
        *(__half*)((char*)smA + off) = __float2half_rn(av);
        *(__half*)((char*)smB + off) = __float2half_rn(bv);
    }
    __syncthreads();

    const int a_row_l = (lane & 15);
    const int a_col_l = (lane & 16) ? 16 : 0;
    const int b_row_l = (lane & 7) + ((lane & 16) ? 8 : 0);
    const int b_col_l = (lane & 8) ? 16 : 0;

    float acc[4][4][4];
    #pragma unroll
    for (int mi = 0; mi < 4; ++mi)
        #pragma unroll
        for (int ni = 0; ni < 4; ++ni)
            #pragma unroll
            for (int j = 0; j < 4; ++j) acc[mi][ni][j] = 0.f;

    #pragma unroll
    for (int ks = 0; ks < 4; ++ks) {
        uint32_t a[4][4];
        uint32_t b[2][4];
        #pragma unroll
        for (int mi = 0; mi < 4; ++mi) {
            const int row = wm * 64 + mi * 16 + a_row_l;
            const int col = ks * 32 + a_col_l;
            const uint32_t addr = sA + SMEM_SWIZZLE_128B((uint32_t)(row * 128 + col));
            ldm_x4(a[mi][0], a[mi][1], a[mi][2], a[mi][3], addr);
        }
        #pragma unroll
        for (int np = 0; np < 2; ++np) {
            const int row = wn * 32 + np * 16 + b_row_l;
            const int col = ks * 32 + b_col_l;
            const uint32_t addr = sB + SMEM_SWIZZLE_128B((uint32_t)(row * 128 + col));
            ldm_x4(b[np][0], b[np][1], b[np][2], b[np][3], addr);
        }
        #pragma unroll
        for (int mi = 0; mi < 4; ++mi)
            #pragma unroll
            for (int ni = 0; ni < 4; ++ni) {
                const uint32_t b0 = b[ni >> 1][(ni & 1) * 2];
                const uint32_t b1 = b[ni >> 1][(ni & 1) * 2 + 1];
                mma_f16(acc[mi][ni][0], acc[mi][ni][1], acc[mi][ni][2], acc[mi][ni][3],
                        a[mi][0], a[mi][1], a[mi][2], a[mi][3], b0, b1);
            }
    }

    // Epilogue: W_eff = acc + Wb; store fp16 (half2 per pair).
    #pragma unroll
    for (int ni = 0; ni < 4; ++ni) {
        const int n = d0 + wn * 32 + ni * 8 + (lane & 3) * 2;
        #pragma unroll
        for (int mi = 0; mi < 4; ++mi) {
            const int m = o0 + wm * 64 + mi * 16 + (lane >> 2);
            const float* wb0 = Wb + (size_t)m * DIN + n;
            const float* wb1 = Wb + (size_t)(m + 8) * DIN + n;
            __half2 h0, h1;
            h0.x = __float2half_rn(acc[mi][ni][0] + wb0[0]);
            h0.y = __float2half_rn(acc[mi][ni][1] + wb0[1]);
            h1.x = __float2half_rn(acc[mi][ni][2] + wb1[0]);
            h1.y = __float2half_rn(acc[mi][ni][3] + wb1[1]);
            *(__half2*)(g_wh + (size_t)m * DIN + n)       = h0;
            *(__half2*)(g_wh + (size_t)(m + 8) * DIN + n) = h1;
        }
    }
}

// ============================================================================
// Kernel 4: convert x to fp16.
// ============================================================================
__global__ void k_cvt_x(const float* __restrict__ x) {
    size_t idx = (size_t)blockIdx.x * blockDim.x + threadIdx.x;  // over MROWS*DIN/4
    float4 v = ((const float4*)x)[idx];
    __half2 h01 = __floats2half2_rn(v.x, v.y);
    __half2 h23 = __floats2half2_rn(v.z, v.w);
    ((__half2*)g_xh)[2*idx]   = h01;
    ((__half2*)g_xh)[2*idx+1] = h23;
}

// ============================================================================
// Kernel 5: GEMM (R12 config — frozen at its plateau).
// ============================================================================
#define BM 128
#define BN 128
#define BK 64
#define STAGE_BYTES 32768   // A 16KB + B 16KB
#define NSTAGE 3
#define GEMM_SMEM   (STAGE_BYTES * NSTAGE)   // 98304
#define ITERS 64            // 4096 / 64

__global__ __launch_bounds__(256, 2) void k_gemm(const float* __restrict__ bias,
                                                 float* __restrict__ out) {
    extern __shared__ __align__(1024) unsigned char dynsmem[];
    const uint32_t smem_base = smem_u32(dynsmem);

    const int tid = threadIdx.x;
    const int wid = tid >> 5;
    const int lane = tid & 31;
    const int wm = wid & 1;          // 2 warps along M
    const int wn = wid >> 1;         // 4 warps along N
    const int m0 = blockIdx.y * BM;  // gridDim.y = 64
    const int n0 = blockIdx.x * BN;  // gridDim.x = 32

    const int ld_row = tid >> 3;          // 0..31 (+32*i)
    const int ld_c   = tid & 7;           // 16B column within 128B row

    float acc[4][4][4];                   // [mi][ni][reg]
    #pragma unroll
    for (int mi = 0; mi < 4; ++mi)
        #pragma unroll
        for (int ni = 0; ni < 4; ++ni)
            #pragma unroll
            for (int j = 0; j < 4; ++j) acc[mi][ni][j] = 0.f;

    const int a_row_l = (lane & 15);
    const int a_col_l = (lane & 16) ? 16 : 0;
    const int b_row_l = (lane & 7) + ((lane & 16) ? 8 : 0);
    const int b_col_l = (lane & 8) ? 16 : 0;

    const __half* Ap0 = g_xh + (size_t)m0 * DIN;
    const __half* Bp0 = g_wh + (size_t)n0 * DIN;

    auto issue_part = [&](int it, int slot, int part) {
        const int kc = it << 6;
        const int row = ld_row + part * 32;
        const uint32_t off = SMEM_SWIZZLE_128B((uint32_t)(row * 128 + ld_c * 16));
        const uint32_t sAb = smem_base + (uint32_t)slot * STAGE_BYTES;
        cp_async16(sAb + off,         Ap0 + kc + (size_t)row * DIN + ld_c * 8);
        cp_async16(sAb + 16384 + off, Bp0 + kc + (size_t)row * DIN + ld_c * 8);
    };
    auto issue_full = [&](int it, int slot) {
        #pragma unroll
        for (int p = 0; p < 4; ++p) issue_part(it, slot, p);
        cp_commit();
    };

    issue_full(0, 0);
    issue_full(1, 1);

    int slot = 0;        // slot of iter 'it'
    for (int it = 0; it < ITERS; ++it) {
        if (it + 1 < ITERS) cp_wait<1>();   // oldest (stage it) complete
        else                cp_wait<0>();
        __syncthreads();                    // compute(it-1) done; its slot is free

        const bool do_issue = (it + 2 < ITERS);
        int ns = slot + 2; if (ns >= NSTAGE) ns -= NSTAGE;

        const uint32_t sAb = smem_base + (uint32_t)slot * STAGE_BYTES;
        const uint32_t sBb = sAb + 16384;

        #pragma unroll
        for (int ks = 0; ks < 4; ++ks) {
            if (do_issue) issue_part(it + 2, ns, ks);   // spread STS across ks
            uint32_t a[4][4];
            uint32_t b[2][4];
            #pragma unroll
            for (int mi = 0; mi < 4; ++mi) {
                const int row = wm * 64 + mi * 16 + a_row_l;
                const int col = ks * 32 + a_col_l;
                const uint32_t addr = sAb + SMEM_SWIZZLE_128B((uint32_t)(row * 128 + col));
                ldm_x4(a[mi][0], a[mi][1], a[mi][2], a[mi][3], addr);
            }
            #pragma unroll
            for (int np = 0; np < 2; ++np) {
                const int row = wn * 32 + np * 16 + b_row_l;
                const int col = ks * 32 + b_col_l;
                const uint32_t addr = sBb + SMEM_SWIZZLE_128B((uint32_t)(row * 128 + col));
                ldm_x4(b[np][0], b[np][1], b[np][2], b[np][3], addr);
            }
            #pragma unroll
            for (int mi = 0; mi < 4; ++mi)
                #pragma unroll
                for (int ni = 0; ni < 4; ++ni) {
                    const uint32_t b0 = b[ni >> 1][(ni & 1) * 2];
                    const uint32_t b1 = b[ni >> 1][(ni & 1) * 2 + 1];
                    mma_f16(acc[mi][ni][0], acc[mi][ni][1], acc[mi][ni][2], acc[mi][ni][3],
                            a[mi][0], a[mi][1], a[mi][2], a[mi][3], b0, b1);
                }
        }
        if (do_issue) cp_commit();
        if (++slot >= NSTAGE) slot = 0;
    }

    // Epilogue: direct stores, float2 per fragment row, +bias.
    #pragma unroll
    for (int ni = 0; ni < 4; ++ni) {
        const int n = n0 + wn * 32 + ni * 8 + (lane & 3) * 2;
        const float bv0 = bias[n];
        const float bv1 = bias[n + 1];
        #pragma unroll
        for (int mi = 0; mi < 4; ++mi) {
            const int m = m0 + wm * 64 + mi * 16 + (lane >> 2);
            float2 v0 = make_float2(acc[mi][ni][0] + bv0, acc[mi][ni][1] + bv1);
            float2 v1 = make_float2(acc[mi][ni][2] + bv0, acc[mi][ni][3] + bv1);
            *(float2*)(out + (size_t)m * DOUT + n)       = v0;
            *(float2*)(out + (size_t)(m + 8) * DOUT + n) = v1;
        }
    }
}

// ============================================================================
// launch — single stream, 6 nodes.
// ============================================================================
extern "C" void kernel_launch(void* const* d_in, const int* in_sizes, int n_in,
                              void* d_out, int out_size) {
    const float* x      = (const float*)d_in[0];
    const float* W_base = (const float*)d_in[1];
    const float* b_base = (const float*)d_in[2];
    const float* enc0   = (const float*)d_in[3];
    const float* enc1   = (const float*)d_in[4];
    const float* coefs0 = (const float*)d_in[5];
    const float* coefs1 = (const float*)d_in[6];
    const void*  mask0  = d_in[7];
    const void*  mask1  = d_in[8];
    float* out = (float*)d_out;

    static int smem_set = 0;
    if (!smem_set) {
        cudaFuncSetAttribute(k_gemm, cudaFuncAttributeMaxDynamicSharedMemorySize, GEMM_SMEM);
        smem_set = 1;
    }

    // 0) detect mask dtype (g_viol statically zeroed; ORs are idempotent)
    k_detect<<<(NEXP * DOUT * R0 / 4) / 256, 256>>>((const unsigned int*)mask0);
    // 1) fused: masked coefficient sums + DC/Nyquist init of g_fw
    k_prep<<<(2 * DOUT * RTOT + 255) / 256, 256>>>(coefs0, coefs1, mask0, mask1);
    // 2) Fourier transform of the 40 coefficient columns along O
    k_transform<<<dim3(32, 16), 128>>>();
    // 3) fold rank-40 update via tensor-core K=40 GEMM (DRAM-bound now)
    k_build_w_mma<<<dim3(32, 32), 256>>>(W_base, enc0, enc1);
    // 4) convert activations to fp16
    k_cvt_x<<<(MROWS * DIN / 4) / 256, 256>>>(x);
    // 5) single-pass fp16 GEMM (R12 config)
    k_gemm<<<dim3(32, 64), 256, GEMM_SMEM>>>(b_base, out);
}

// round 16
// speedup vs baseline: 1.0046x; 1.0046x over previous
#include <cuda_runtime.h>
#include <cuda_bf16.h>
#include <cuda_fp16.h>
#include <cstdint>

// ---------------- problem constants ----------------
#define DIN   4096
#define DOUT  4096
#define MROWS 8192          // B*S = 4*2048
#define R0    32
#define R1    8
#define RTOT  40
#define NEXP  3
#define SCALING 0.5f        // 16/32

// ---------------- device scratch ----------------
__device__ __align__(256) float  g_sumw[DOUT * RTOT];   // masked coef sums  [O, 40]
__device__ __align__(256) float  g_fw  [DOUT * RTOT];   // fourier-transformed [O, 40]
__device__ __align__(256) __half g_wh[(size_t)DOUT * DIN];   // W_eff fp16
__device__ __align__(256) __half g_xh[(size_t)MROWS * DIN];  // x fp16
// statically zero-initialized; k_detect only ORs input-derived bits (idempotent)
__device__ unsigned int g_viol[2] = {0u, 0u};

// ---------------- helpers ----------------
__device__ __forceinline__ uint32_t smem_u32(const void* p) {
    uint32_t a;
    asm("{ .reg .u64 t; cvta.to.shared.u64 t, %1; cvt.u32.u64 %0, t; }" : "=r"(a) : "l"(p));
    return a;
}
#define SMEM_SWIZZLE_128B(off) ((off) ^ (((off) >> 3) & 0x70))

__device__ __forceinline__ void cp_async16(uint32_t saddr, const void* gaddr) {
    asm volatile("cp.async.cg.shared.global [%0], [%1], 16;" :: "r"(saddr), "l"(gaddr));
}
__device__ __forceinline__ void cp_commit() {
    asm volatile("cp.async.commit_group;" ::: "memory");
}
template <int N>
__device__ __forceinline__ void cp_wait() {
    asm volatile("cp.async.wait_group %0;" :: "n"(N) : "memory");
}

__device__ __forceinline__ void ldm_x4(uint32_t& r0, uint32_t& r1, uint32_t& r2, uint32_t& r3,
                                       uint32_t addr) {
    asm volatile("ldmatrix.sync.aligned.m8n8.x4.shared.b16 {%0,%1,%2,%3}, [%4];"
                 : "=r"(r0), "=r"(r1), "=r"(r2), "=r"(r3) : "r"(addr));
}

__device__ __forceinline__ void mma_f16(float& c0, float& c1, float& c2, float& c3,
                                        uint32_t a0, uint32_t a1, uint32_t a2, uint32_t a3,
                                        uint32_t b0, uint32_t b1) {
    asm volatile(
        "mma.sync.aligned.m16n8k16.row.col.f32.f16.f16.f32 "
        "{%0,%1,%2,%3}, {%4,%5,%6,%7}, {%8,%9}, {%0,%1,%2,%3};"
        : "+f"(c0), "+f"(c1), "+f"(c2), "+f"(c3)
        : "r"(a0), "r"(a1), "r"(a2), "r"(a3), "r"(b0), "r"(b1));
}

// ============================================================================
// Kernel 0: mask dtype detection (uint8 / int32 / float32 bools).
// ============================================================================
__global__ void k_detect(const unsigned int* __restrict__ w) {
    unsigned int v = w[blockIdx.x * blockDim.x + threadIdx.x];
    if (v > 1u) atomicOr(&g_viol[0], 1u);
    if (v != 0u && v != 0x3f800000u) atomicOr(&g_viol[1], 1u);
}

__device__ __forceinline__ bool mask_at(const void* m, int j, int mode) {
    if (mode == 1) return ((const int*)m)[j] != 0;
    if (mode == 2) return ((const float*)m)[j] != 0.f;
    return ((const unsigned char*)m)[j] != 0;
}

__device__ __forceinline__ float masked_sum(const float* c, const void* m,
                                            int o, int rr, int R, int mode) {
    float s = 0.f;
    #pragma unroll
    for (int e = 0; e < NEXP; ++e) {
        int j = e * DOUT * R + o * R + rr;
        s += mask_at(m, j, mode) ? c[j] : 0.f;
    }
    return s;
}

// ============================================================================
// Kernel 1 (FUSED): masked coefficient sums + DC/Nyquist init of g_fw.
// ============================================================================
__global__ void k_prep(const float* __restrict__ c0, const float* __restrict__ c1,
                       const void* __restrict__ m0, const void* __restrict__ m1) {
    int idx = blockIdx.x * blockDim.x + threadIdx.x;
    const int total = DOUT * RTOT;
    const int mode = (g_viol[0] == 0u) ? 1 : ((g_viol[1] == 0u) ? 2 : 0);
    if (idx < total) {
        int o = idx / RTOT, r = idx % RTOT;
        float s = (r < R0) ? masked_sum(c0, m0, o, r, R0, mode)
                           : masked_sum(c1, m1, o, r - R0, R1, mode);
        g_sumw[o * RTOT + r] = s;
    } else if (idx < 2 * total) {
        int j = idx - total;
        int t = j / RTOT, r = j % RTOT;
        float s0, sN;
        if (r < R0) {
            s0 = masked_sum(c0, m0, 0, r, R0, mode);
            sN = masked_sum(c0, m0, DOUT - 1, r, R0, mode);
        } else {
            s0 = masked_sum(c1, m1, 0, r - R0, R1, mode);
            sN = masked_sum(c1, m1, DOUT - 1, r - R0, R1, mode);
        }
        const float inv = 0.015625f;                   // 1/sqrt(4096)
        float sgn = (t & 1) ? -inv : inv;
        g_fw[j] = s0 * inv + sN * sgn;
    }
}

// ============================================================================
// Kernel 2: frequency-parallel Fourier accumulation with rotation recurrence.
// ============================================================================
__global__ void k_transform() {
    __shared__ float sc[128 * RTOT];       // 64 freqs (cos,sin rows) at a time
    int t = blockIdx.x * 128 + threadIdx.x;
    float acc[RTOT];
    #pragma unroll
    for (int r = 0; r < RTOT; ++r) acc[r] = 0.f;

    const float TWO_PI_OVER_N = 0.00153398078788564123f;
    float cd, sd;
    {
        int kt = t & 4095;
        int kt2 = (kt <= 2048) ? kt : (kt - 4096);
        __sincosf((float)kt2 * TWO_PI_OVER_N, &sd, &cd);
    }

    #pragma unroll
    for (int half = 0; half < 2; ++half) {
        int fs = 1 + blockIdx.y * 128 + half * 64;
        int nf = 2048 - fs; if (nf > 64) nf = 64;      // f max = 2047
        if (nf <= 0) break;
        int row0 = 2 * fs - 1;
        __syncthreads();
        for (int i = threadIdx.x; i < 2 * nf; i += 128) {
            const float4* src = (const float4*)(g_sumw + (size_t)(row0 + i) * RTOT);
            float4* dst = (float4*)(sc + i * RTOT);
            #pragma unroll
            for (int q = 0; q < 10; ++q) dst[q] = src[q];
        }
        __syncthreads();

        float cv, sv;
        {
            int k = (fs * t) & 4095;
            int k2 = (k <= 2048) ? k : (k - 4096);
            __sincosf((float)k2 * TWO_PI_OVER_N, &sv, &cv);
        }

        for (int j = 0; j < nf; ++j) {
            const float4* cc = (const float4*)(sc + (2 * j) * RTOT);
            const float4* ss = (const float4*)(sc + (2 * j + 1) * RTOT);
            #pragma unroll
            for (int q = 0; q < 10; ++q) {
                float4 a = cc[q]; float4 b = ss[q];
                acc[4*q+0] += a.x * cv + b.x * sv;
                acc[4*q+1] += a.y * cv + b.y * sv;
                acc[4*q+2] += a.z * cv + b.z * sv;
                acc[4*q+3] += a.w * cv + b.w * sv;
            }
            float ncv = cv * cd - sv * sd;
            sv = sv * cd + cv * sd;
            cv = ncv;
        }
    }
    const float s2 = 0.02209708691207961102f;          // sqrt(2/4096)
    float* dst = g_fw + (size_t)t * RTOT;
    #pragma unroll
    for (int r = 0; r < RTOT; ++r) atomicAdd(dst + r, acc[r] * s2);
}

// ============================================================================
// Kernel 3 (tensor-core, COALESCED fills): W_eff = W_base + (0.5*FW)@enc, fp16.
// A-tile fill: k-fastest  -> g_fw reads contiguous per warp.
// B-tile fill: d-fastest  -> enc reads contiguous per warp (was 16KB-strided:
//   the round-15 bug; 32x transaction amplification made the kernel 80us).
// ============================================================================
__global__ __launch_bounds__(256) void k_build_w_mma(const float* __restrict__ Wb,
                                                     const float* __restrict__ enc0,
                                                     const float* __restrict__ enc1) {
    __shared__ __align__(1024) __half smA[128 * 64];   // 16 KB  (o x k, 128B rows)
    __shared__ __align__(1024) __half smB[128 * 64];   // 16 KB  (d x k)

    const int tid = threadIdx.x;
    const int wid = tid >> 5;
    const int lane = tid & 31;
    const int wm = wid & 1;          // 2 warps along M (o)
    const int wn = wid >> 1;         // 4 warps along N (d)
    const int o0 = blockIdx.y * 128; // gridDim.y = 32
    const int d0 = blockIdx.x * 128; // gridDim.x = 32

    const uint32_t sA = smem_u32(smA);
    const uint32_t sB = smem_u32(smB);

    // A fill (k fastest): warp reads 32 consecutive g_fw floats.
    for (int i = tid; i < 128 * 64; i += 256) {
        const int row = i >> 6;          // o_local
        const int k   = i & 63;
        const uint32_t off = SMEM_SWIZZLE_128B((uint32_t)(row * 128 + k * 2));
        float av = (k < RTOT) ? 0.5f * g_fw[(size_t)(o0 + row) * RTOT + k] : 0.f;
        *(__half*)((char*)smA + off) = __float2half_rn(av);
    }
    // B fill (d fastest): warp reads 32 consecutive enc floats of one row.
    for (int i = tid; i < 128 * 64; i += 256) {
        const int d = i & 127;           // d_local (row of B tile)
        const int k = i >> 7;
        const uint32_t off = SMEM_SWIZZLE_128B((uint32_t)(d * 128 + k * 2));
        float bv = 0.f;
        if (k < R0)        bv = enc0[(size_t)k * DIN + d0 + d];
        else if (k < RTOT) bv = enc1[(size_t)(k - R0) * DIN + d0 + d];
        *(__half*)((char*)smB + off) = __float2half_rn(bv);
    }
    __syncthreads();

    const int a_row_l = (lane & 15);
    const int a_col_l = (lane & 16) ? 16 : 0;
    const int b_row_l = (lane & 7) + ((lane & 16) ? 8 : 0);
    const int b_col_l = (lane & 8) ? 16 : 0;

    float acc[4][4][4];
    #pragma unroll
    for (int mi = 0; mi < 4; ++mi)
        #pragma unroll
        for (int ni = 0; ni < 4; ++ni)
            #pragma unroll
            for (int j = 0; j < 4; ++j) acc[mi][ni][j] = 0.f;

    #pragma unroll
    for (int ks = 0; ks < 4; ++ks) {
        uint32_t a[4][4];
        uint32_t b[2][4];
        #pragma unroll
        for (int mi = 0; mi < 4; ++mi) {
            const int row = wm * 64 + mi * 16 + a_row_l;
            const int col = ks * 32 + a_col_l;
            const uint32_t addr = sA + SMEM_SWIZZLE_128B((uint32_t)(row * 128 + col));
            ldm_x4(a[mi][0], a[mi][1], a[mi][2], a[mi][3], addr);
        }
        #pragma unroll
        for (int np = 0; np < 2; ++np) {
            const int row = wn * 32 + np * 16 + b_row_l;
            const int col = ks * 32 + b_col_l;
            const uint32_t addr = sB + SMEM_SWIZZLE_128B((uint32_t)(row * 128 + col));
            ldm_x4(b[np][0], b[np][1], b[np][2], b[np][3], addr);
        }
        #pragma unroll
        for (int mi = 0; mi < 4; ++mi)
            #pragma unroll
            for (int ni = 0; ni < 4; ++ni) {
                const uint32_t b0 = b[ni >> 1][(ni & 1) * 2];
                const uint32_t b1 = b[ni >> 1][(ni & 1) * 2 + 1];
                mma_f16(acc[mi][ni][0], acc[mi][ni][1], acc[mi][ni][2], acc[mi][ni][3],
                        a[mi][0], a[mi][1], a[mi][2], a[mi][3], b0, b1);
            }
    }

    // Epilogue: W_eff = acc + Wb; store fp16 (half2 per pair).
    #pragma unroll
    for (int ni = 0; ni < 4; ++ni) {
        const int n = d0 + wn * 32 + ni * 8 + (lane & 3) * 2;
        #pragma unroll
        for (int mi = 0; mi < 4; ++mi) {
            const int m = o0 + wm * 64 + mi * 16 + (lane >> 2);
            const float* wb0 = Wb + (size_t)m * DIN + n;
            const float* wb1 = Wb + (size_t)(m + 8) * DIN + n;
            __half2 h0, h1;
            h0.x = __float2half_rn(acc[mi][ni][0] + wb0[0]);
            h0.y = __float2half_rn(acc[mi][ni][1] + wb0[1]);
            h1.x = __float2half_rn(acc[mi][ni][2] + wb1[0]);
            h1.y = __float2half_rn(acc[mi][ni][3] + wb1[1]);
            *(__half2*)(g_wh + (size_t)m * DIN + n)       = h0;
            *(__half2*)(g_wh + (size_t)(m + 8) * DIN + n) = h1;
        }
    }
}

// ============================================================================
// Kernel 4: convert x to fp16.
// ============================================================================
__global__ void k_cvt_x(const float* __restrict__ x) {
    size_t idx = (size_t)blockIdx.x * blockDim.x + threadIdx.x;  // over MROWS*DIN/4
    float4 v = ((const float4*)x)[idx];
    __half2 h01 = __floats2half2_rn(v.x, v.y);
    __half2 h23 = __floats2half2_rn(v.z, v.w);
    ((__half2*)g_xh)[2*idx]   = h01;
    ((__half2*)g_xh)[2*idx+1] = h23;
}

// ============================================================================
// Kernel 5: GEMM (R12 config — frozen at its plateau).
// ============================================================================
#define BM 128
#define BN 128
#define BK 64
#define STAGE_BYTES 32768   // A 16KB + B 16KB
#define NSTAGE 3
#define GEMM_SMEM   (STAGE_BYTES * NSTAGE)   // 98304
#define ITERS 64            // 4096 / 64

__global__ __launch_bounds__(256, 2) void k_gemm(const float* __restrict__ bias,
                                                 float* __restrict__ out) {
    extern __shared__ __align__(1024) unsigned char dynsmem[];
    const uint32_t smem_base = smem_u32(dynsmem);

    const int tid = threadIdx.x;
    const int wid = tid >> 5;
    const int lane = tid & 31;
    const int wm = wid & 1;          // 2 warps along M
    const int wn = wid >> 1;         // 4 warps along N
    const int m0 = blockIdx.y * BM;  // gridDim.y = 64
    const int n0 = blockIdx.x * BN;  // gridDim.x = 32

    const int ld_row = tid >> 3;          // 0..31 (+32*i)
    const int ld_c   = tid & 7;           // 16B column within 128B row

    float acc[4][4][4];                   // [mi][ni][reg]
    #pragma unroll
    for (int mi = 0; mi < 4; ++mi)
        #pragma unroll
        for (int ni = 0; ni < 4; ++ni)
            #pragma unroll
            for (int j = 0; j < 4; ++j) acc[mi][ni][j] = 0.f;

    const int a_row_l = (lane & 15);
    const int a_col_l = (lane & 16) ? 16 : 0;
    const int b_row_l = (lane & 7) + ((lane & 16) ? 8 : 0);
    const int b_col_l = (lane & 8) ? 16 : 0;

    const __half* Ap0 = g_xh + (size_t)m0 * DIN;
    const __half* Bp0 = g_wh + (size_t)n0 * DIN;

    auto issue_part = [&](int it, int slot, int part) {
        const int kc = it << 6;
        const int row = ld_row + part * 32;
        const uint32_t off = SMEM_SWIZZLE_128B((uint32_t)(row * 128 + ld_c * 16));
        const uint32_t sAb = smem_base + (uint32_t)slot * STAGE_BYTES;
        cp_async16(sAb + off,         Ap0 + kc + (size_t)row * DIN + ld_c * 8);
        cp_async16(sAb + 16384 + off, Bp0 + kc + (size_t)row * DIN + ld_c * 8);
    };
    auto issue_full = [&](int it, int slot) {
        #pragma unroll
        for (int p = 0; p < 4; ++p) issue_part(it, slot, p);
        cp_commit();
    };

    issue_full(0, 0);
    issue_full(1, 1);

    int slot = 0;        // slot of iter 'it'
    for (int it = 0; it < ITERS; ++it) {
        if (it + 1 < ITERS) cp_wait<1>();   // oldest (stage it) complete
        else                cp_wait<0>();
        __syncthreads();                    // compute(it-1) done; its slot is free

        const bool do_issue = (it + 2 < ITERS);
        int ns = slot + 2; if (ns >= NSTAGE) ns -= NSTAGE;

        const uint32_t sAb = smem_base + (uint32_t)slot * STAGE_BYTES;
        const uint32_t sBb = sAb + 16384;

        #pragma unroll
        for (int ks = 0; ks < 4; ++ks) {
            if (do_issue) issue_part(it + 2, ns, ks);   // spread STS across ks
            uint32_t a[4][4];
            uint32_t b[2][4];
            #pragma unroll
            for (int mi = 0; mi < 4; ++mi) {
                const int row = wm * 64 + mi * 16 + a_row_l;
                const int col = ks * 32 + a_col_l;
                const uint32_t addr = sAb + SMEM_SWIZZLE_128B((uint32_t)(row * 128 + col));
                ldm_x4(a[mi][0], a[mi][1], a[mi][2], a[mi][3], addr);
            }
            #pragma unroll
            for (int np = 0; np < 2; ++np) {
                const int row = wn * 32 + np * 16 + b_row_l;
                const int col = ks * 32 + b_col_l;
                const uint32_t addr = sBb + SMEM_SWIZZLE_128B((uint32_t)(row * 128 + col));
                ldm_x4(b[np][0], b[np][1], b[np][2], b[np][3], addr);
            }
            #pragma unroll
            for (int mi = 0; mi < 4; ++mi)
                #pragma unroll
                for (int ni = 0; ni < 4; ++ni) {
                    const uint32_t b0 = b[ni >> 1][(ni & 1) * 2];
                    const uint32_t b1 = b[ni >> 1][(ni & 1) * 2 + 1];
                    mma_f16(acc[mi][ni][0], acc[mi][ni][1], acc[mi][ni][2], acc[mi][ni][3],
                            a[mi][0], a[mi][1], a[mi][2], a[mi][3], b0, b1);
                }
        }
        if (do_issue) cp_commit();
        if (++slot >= NSTAGE) slot = 0;
    }

    // Epilogue: direct stores, float2 per fragment row, +bias.
    #pragma unroll
    for (int ni = 0; ni < 4; ++ni) {
        const int n = n0 + wn * 32 + ni * 8 + (lane & 3) * 2;
        const float bv0 = bias[n];
        const float bv1 = bias[n + 1];
        #pragma unroll
        for (int mi = 0; mi < 4; ++mi) {
            const int m = m0 + wm * 64 + mi * 16 + (lane >> 2);
            float2 v0 = make_float2(acc[mi][ni][0] + bv0, acc[mi][ni][1] + bv1);
            float2 v1 = make_float2(acc[mi][ni][2] + bv0, acc[mi][ni][3] + bv1);
            *(float2*)(out + (size_t)m * DOUT + n)       = v0;
            *(float2*)(out + (size_t)(m + 8) * DOUT + n) = v1;
        }
    }
}

// ============================================================================
// launch — single stream, 6 nodes.
// ============================================================================
extern "C" void kernel_launch(void* const* d_in, const int* in_sizes, int n_in,
                              void* d_out, int out_size) {
    const float* x      = (const float*)d_in[0];
    const float* W_base = (const float*)d_in[1];
    const float* b_base = (const float*)d_in[2];
    const float* enc0   = (const float*)d_in[3];
    const float* enc1   = (const float*)d_in[4];
    const float* coefs0 = (const float*)d_in[5];
    const float* coefs1 = (const float*)d_in[6];
    const void*  mask0  = d_in[7];
    const void*  mask1  = d_in[8];
    float* out = (float*)d_out;

    static int smem_set = 0;
    if (!smem_set) {
        cudaFuncSetAttribute(k_gemm, cudaFuncAttributeMaxDynamicSharedMemorySize, GEMM_SMEM);
        smem_set = 1;
    }

    // 0) detect mask dtype (g_viol statically zeroed; ORs are idempotent)
    k_detect<<<(NEXP * DOUT * R0 / 4) / 256, 256>>>((const unsigned int*)mask0);
    // 1) fused: masked coefficient sums + DC/Nyquist init of g_fw
    k_prep<<<(2 * DOUT * RTOT + 255) / 256, 256>>>(coefs0, coefs1, mask0, mask1);
    // 2) Fourier transform of the 40 coefficient columns along O
    k_transform<<<dim3(32, 16), 128>>>();
    // 3) fold rank-40 update via tensor-core K=40 GEMM (coalesced fills)
    k_build_w_mma<<<dim3(32, 32), 256>>>(W_base, enc0, enc1);
    // 4) convert activations to fp16
    k_cvt_x<<<(MROWS * DIN / 4) / 256, 256>>>(x);
    // 5) single-pass fp16 GEMM (R12 config)
    k_gemm<<<dim3(32, 64), 256, GEMM_SMEM>>>(b_base, out);
}

// round 17
// speedup vs baseline: 1.0551x; 1.0502x over previous
#include <cuda_runtime.h>
#include <cuda_bf16.h>
#include <cuda_fp16.h>
#include <cstdint>

// ---------------- problem constants ----------------
#define DIN   4096
#define DOUT  4096
#define MROWS 8192          // B*S = 4*2048
#define R0    32
#define R1    8
#define RTOT  40
#define NEXP  3
#define SCALING 0.5f        // 16/32

// ---------------- device scratch ----------------
__device__ __align__(256) float  g_sumw[DOUT * RTOT];   // masked coef sums  [O, 40]
__device__ __align__(256) float  g_fw  [DOUT * RTOT];   // fourier-transformed [O, 40]
__device__ __align__(256) __half g_wh[(size_t)DOUT * DIN];   // W_eff fp16
__device__ __align__(256) __half g_xh[(size_t)MROWS * DIN];  // x fp16
// statically zero-initialized; k_detect only ORs input-derived bits (idempotent)
__device__ unsigned int g_viol[2] = {0u, 0u};

// ---------------- helpers ----------------
__device__ __forceinline__ uint32_t smem_u32(const void* p) {
    uint32_t a;
    asm("{ .reg .u64 t; cvta.to.shared.u64 t, %1; cvt.u32.u64 %0, t; }" : "=r"(a) : "l"(p));
    return a;
}
#define SMEM_SWIZZLE_128B(off) ((off) ^ (((off) >> 3) & 0x70))

__device__ __forceinline__ void cp_async16(uint32_t saddr, const void* gaddr) {
    asm volatile("cp.async.cg.shared.global [%0], [%1], 16;" :: "r"(saddr), "l"(gaddr));
}
__device__ __forceinline__ void cp_commit() {
    asm volatile("cp.async.commit_group;" ::: "memory");
}
template <int N>
__device__ __forceinline__ void cp_wait() {
    asm volatile("cp.async.wait_group %0;" :: "n"(N) : "memory");
}

__device__ __forceinline__ void ldm_x4(uint32_t& r0, uint32_t& r1, uint32_t& r2, uint32_t& r3,
                                       uint32_t addr) {
    asm volatile("ldmatrix.sync.aligned.m8n8.x4.shared.b16 {%0,%1,%2,%3}, [%4];"
                 : "=r"(r0), "=r"(r1), "=r"(r2), "=r"(r3) : "r"(addr));
}

__device__ __forceinline__ void mma_f16(float& c0, float& c1, float& c2, float& c3,
                                        uint32_t a0, uint32_t a1, uint32_t a2, uint32_t a3,
                                        uint32_t b0, uint32_t b1) {
    asm volatile(
        "mma.sync.aligned.m16n8k16.row.col.f32.f16.f16.f32 "
        "{%0,%1,%2,%3}, {%4,%5,%6,%7}, {%8,%9}, {%0,%1,%2,%3};"
        : "+f"(c0), "+f"(c1), "+f"(c2), "+f"(c3)
        : "r"(a0), "r"(a1), "r"(a2), "r"(a3), "r"(b0), "r"(b1));
}

// ============================================================================
// Kernel 0: mask dtype detection (uint8 / int32 / float32 bools).
// ============================================================================
__global__ void k_detect(const unsigned int* __restrict__ w) {
    unsigned int v = w[blockIdx.x * blockDim.x + threadIdx.x];
    if (v > 1u) atomicOr(&g_viol[0], 1u);
    if (v != 0u && v != 0x3f800000u) atomicOr(&g_viol[1], 1u);
}

__device__ __forceinline__ bool mask_at(const void* m, int j, int mode) {
    if (mode == 1) return ((const int*)m)[j] != 0;
    if (mode == 2) return ((const float*)m)[j] != 0.f;
    return ((const unsigned char*)m)[j] != 0;
}

__device__ __forceinline__ float masked_sum(const float* c, const void* m,
                                            int o, int rr, int R, int mode) {
    float s = 0.f;
    #pragma unroll
    for (int e = 0; e < NEXP; ++e) {
        int j = e * DOUT * R + o * R + rr;
        s += mask_at(m, j, mode) ? c[j] : 0.f;
    }
    return s;
}

// ============================================================================
// Kernel 1 (FUSED): masked coefficient sums + DC/Nyquist init of g_fw.
// ============================================================================
__global__ void k_prep(const float* __restrict__ c0, const float* __restrict__ c1,
                       const void* __restrict__ m0, const void* __restrict__ m1) {
    int idx = blockIdx.x * blockDim.x + threadIdx.x;
    const int total = DOUT * RTOT;
    const int mode = (g_viol[0] == 0u) ? 1 : ((g_viol[1] == 0u) ? 2 : 0);
    if (idx < total) {
        int o = idx / RTOT, r = idx % RTOT;
        float s = (r < R0) ? masked_sum(c0, m0, o, r, R0, mode)
                           : masked_sum(c1, m1, o, r - R0, R1, mode);
        g_sumw[o * RTOT + r] = s;
    } else if (idx < 2 * total) {
        int j = idx - total;
        int t = j / RTOT, r = j % RTOT;
        float s0, sN;
        if (r < R0) {
            s0 = masked_sum(c0, m0, 0, r, R0, mode);
            sN = masked_sum(c0, m0, DOUT - 1, r, R0, mode);
        } else {
            s0 = masked_sum(c1, m1, 0, r - R0, R1, mode);
            sN = masked_sum(c1, m1, DOUT - 1, r - R0, R1, mode);
        }
        const float inv = 0.015625f;                   // 1/sqrt(4096)
        float sgn = (t & 1) ? -inv : inv;
        g_fw[j] = s0 * inv + sN * sgn;
    }
}

// ============================================================================
// Kernel 2: frequency-parallel Fourier accumulation with rotation recurrence.
// ============================================================================
__global__ void k_transform() {
    __shared__ float sc[128 * RTOT];       // 64 freqs (cos,sin rows) at a time
    int t = blockIdx.x * 128 + threadIdx.x;
    float acc[RTOT];
    #pragma unroll
    for (int r = 0; r < RTOT; ++r) acc[r] = 0.f;

    const float TWO_PI_OVER_N = 0.00153398078788564123f;
    float cd, sd;
    {
        int kt = t & 4095;
        int kt2 = (kt <= 2048) ? kt : (kt - 4096);
        __sincosf((float)kt2 * TWO_PI_OVER_N, &sd, &cd);
    }

    #pragma unroll
    for (int half = 0; half < 2; ++half) {
        int fs = 1 + blockIdx.y * 128 + half * 64;
        int nf = 2048 - fs; if (nf > 64) nf = 64;      // f max = 2047
        if (nf <= 0) break;
        int row0 = 2 * fs - 1;
        __syncthreads();
        for (int i = threadIdx.x; i < 2 * nf; i += 128) {
            const float4* src = (const float4*)(g_sumw + (size_t)(row0 + i) * RTOT);
            float4* dst = (float4*)(sc + i * RTOT);
            #pragma unroll
            for (int q = 0; q < 10; ++q) dst[q] = src[q];
        }
        __syncthreads();

        float cv, sv;
        {
            int k = (fs * t) & 4095;
            int k2 = (k <= 2048) ? k : (k - 4096);
            __sincosf((float)k2 * TWO_PI_OVER_N, &sv, &cv);
        }

        for (int j = 0; j < nf; ++j) {
            const float4* cc = (const float4*)(sc + (2 * j) * RTOT);
            const float4* ss = (const float4*)(sc + (2 * j + 1) * RTOT);
            #pragma unroll
            for (int q = 0; q < 10; ++q) {
                float4 a = cc[q]; float4 b = ss[q];
                acc[4*q+0] += a.x * cv + b.x * sv;
                acc[4*q+1] += a.y * cv + b.y * sv;
                acc[4*q+2] += a.z * cv + b.z * sv;
                acc[4*q+3] += a.w * cv + b.w * sv;
            }
            float ncv = cv * cd - sv * sd;
            sv = sv * cd + cv * sd;
            cv = ncv;
        }
    }
    const float s2 = 0.02209708691207961102f;          // sqrt(2/4096)
    float* dst = g_fw + (size_t)t * RTOT;
    #pragma unroll
    for (int r = 0; r < RTOT; ++r) atomicAdd(dst + r, acc[r] * s2);
}

// ============================================================================
// Kernel 3 (tensor-core): W_eff = W_base + (0.5*FW)@enc, fp16.
// R16 finding: the fills were MLP=1 (non-unrolled loop, each STS waiting on
// its LDG -> 32 x 600cyc serial = the whole 76us). This round: compile-time
// trip counts + #pragma unroll so ptxas front-batches all 32 LDGs (MLP~32).
// ============================================================================
__global__ __launch_bounds__(256) void k_build_w_mma(const float* __restrict__ Wb,
                                                     const float* __restrict__ enc0,
                                                     const float* __restrict__ enc1) {
    __shared__ __align__(1024) __half smA[128 * 64];   // 16 KB  (o x k, 128B rows)
    __shared__ __align__(1024) __half smB[128 * 64];   // 16 KB  (d x k)

    const int tid = threadIdx.x;
    const int wid = tid >> 5;
    const int lane = tid & 31;
    const int wm = wid & 1;          // 2 warps along M (o)
    const int wn = wid >> 1;         // 4 warps along N (d)
    const int o0 = blockIdx.y * 128; // gridDim.y = 32
    const int d0 = blockIdx.x * 128; // gridDim.x = 32

    const uint32_t sA = smem_u32(smA);
    const uint32_t sB = smem_u32(smB);

    // ---- batched loads (MLP=32 per operand), then convert+store ----
    float avals[32];
    float bvals[32];
    #pragma unroll
    for (int it = 0; it < 32; ++it) {
        const int i = tid + it * 256;
        // A (k fastest): row = i>>6, k = i&63
        const int ar = i >> 6, ak = i & 63;
        avals[it] = (ak < RTOT) ? 0.5f * g_fw[(size_t)(o0 + ar) * RTOT + ak] : 0.f;
        // B (d fastest): d = i&127, k = i>>7
        const int bd = i & 127, bk = i >> 7;
        float bv = 0.f;
        if (bk < R0)        bv = enc0[(size_t)bk * DIN + d0 + bd];
        else if (bk < RTOT) bv = enc1[(size_t)(bk - R0) * DIN + d0 + bd];
        bvals[it] = bv;
    }
    #pragma unroll
    for (int it = 0; it < 32; ++it) {
        const int i = tid + it * 256;
        const int ar = i >> 6, ak = i & 63;
        const uint32_t aoff = SMEM_SWIZZLE_128B((uint32_t)(ar * 128 + ak * 2));
        *(__half*)((char*)smA + aoff) = __float2half_rn(avals[it]);
        const int bd = i & 127, bk = i >> 7;
        const uint32_t boff = SMEM_SWIZZLE_128B((uint32_t)(bd * 128 + bk * 2));
        *(__half*)((char*)smB + boff) = __float2half_rn(bvals[it]);
    }
    __syncthreads();

    const int a_row_l = (lane & 15);
    const int a_col_l = (lane & 16) ? 16 : 0;
    const int b_row_l = (lane & 7) + ((lane & 16) ? 8 : 0);
    const int b_col_l = (lane & 8) ? 16 : 0;

    float acc[4][4][4];
    #pragma unroll
    for (int mi = 0; mi < 4; ++mi)
        #pragma unroll
        for (int ni = 0; ni < 4; ++ni)
            #pragma unroll
            for (int j = 0; j < 4; ++j) acc[mi][ni][j] = 0.f;

    #pragma unroll
    for (int ks = 0; ks < 4; ++ks) {
        uint32_t a[4][4];
        uint32_t b[2][4];
        #pragma unroll
        for (int mi = 0; mi < 4; ++mi) {
            const int row = wm * 64 + mi * 16 + a_row_l;
            const int col = ks * 32 + a_col_l;
            const uint32_t addr = sA + SMEM_SWIZZLE_128B((uint32_t)(row * 128 + col));
            ldm_x4(a[mi][0], a[mi][1], a[mi][2], a[mi][3], addr);
        }
        #pragma unroll
        for (int np = 0; np < 2; ++np) {
            const int row = wn * 32 + np * 16 + b_row_l;
            const int col = ks * 32 + b_col_l;
            const uint32_t addr = sB + SMEM_SWIZZLE_128B((uint32_t)(row * 128 + col));
            ldm_x4(b[np][0], b[np][1], b[np][2], b[np][3], addr);
        }
        #pragma unroll
        for (int mi = 0; mi < 4; ++mi)
            #pragma unroll
            for (int ni = 0; ni < 4; ++ni) {
                const uint32_t b0 = b[ni >> 1][(ni & 1) * 2];
                const uint32_t b1 = b[ni >> 1][(ni & 1) * 2 + 1];
                mma_f16(acc[mi][ni][0], acc[mi][ni][1], acc[mi][ni][2], acc[mi][ni][3],
                        a[mi][0], a[mi][1], a[mi][2], a[mi][3], b0, b1);
            }
    }

    // Epilogue: W_eff = acc + Wb; store fp16 (half2 per pair). Fully unrolled
    // (loads batch; MLP fine here).
    #pragma unroll
    for (int ni = 0; ni < 4; ++ni) {
        const int n = d0 + wn * 32 + ni * 8 + (lane & 3) * 2;
        #pragma unroll
        for (int mi = 0; mi < 4; ++mi) {
            const int m = o0 + wm * 64 + mi * 16 + (lane >> 2);
            const float2 w0 = *(const float2*)(Wb + (size_t)m * DIN + n);
            const float2 w1 = *(const float2*)(Wb + (size_t)(m + 8) * DIN + n);
            __half2 h0, h1;
            h0.x = __float2half_rn(acc[mi][ni][0] + w0.x);
            h0.y = __float2half_rn(acc[mi][ni][1] + w0.y);
            h1.x = __float2half_rn(acc[mi][ni][2] + w1.x);
            h1.y = __float2half_rn(acc[mi][ni][3] + w1.y);
            *(__half2*)(g_wh + (size_t)m * DIN + n)       = h0;
            *(__half2*)(g_wh + (size_t)(m + 8) * DIN + n) = h1;
        }
    }
}

// ============================================================================
// Kernel 4: convert x to fp16.
// ============================================================================
__global__ void k_cvt_x(const float* __restrict__ x) {
    size_t idx = (size_t)blockIdx.x * blockDim.x + threadIdx.x;  // over MROWS*DIN/4
    float4 v = ((const float4*)x)[idx];
    __half2 h01 = __floats2half2_rn(v.x, v.y);
    __half2 h23 = __floats2half2_rn(v.z, v.w);
    ((__half2*)g_xh)[2*idx]   = h01;
    ((__half2*)g_xh)[2*idx+1] = h23;
}

// ============================================================================
// Kernel 5: GEMM (R12 config — frozen at its plateau).
// ============================================================================
#define BM 128
#define BN 128
#define BK 64
#define STAGE_BYTES 32768   // A 16KB + B 16KB
#define NSTAGE 3
#define GEMM_SMEM   (STAGE_BYTES * NSTAGE)   // 98304
#define ITERS 64            // 4096 / 64

__global__ __launch_bounds__(256, 2) void k_gemm(const float* __restrict__ bias,
                                                 float* __restrict__ out) {
    extern __shared__ __align__(1024) unsigned char dynsmem[];
    const uint32_t smem_base = smem_u32(dynsmem);

    const int tid = threadIdx.x;
    const int wid = tid >> 5;
    const int lane = tid & 31;
    const int wm = wid & 1;          // 2 warps along M
    const int wn = wid >> 1;         // 4 warps along N
    const int m0 = blockIdx.y * BM;  // gridDim.y = 64
    const int n0 = blockIdx.x * BN;  // gridDim.x = 32

    const int ld_row = tid >> 3;          // 0..31 (+32*i)
    const int ld_c   = tid & 7;           // 16B column within 128B row

    float acc[4][4][4];                   // [mi][ni][reg]
    #pragma unroll
    for (int mi = 0; mi < 4; ++mi)
        #pragma unroll
        for (int ni = 0; ni < 4; ++ni)
            #pragma unroll
            for (int j = 0; j < 4; ++j) acc[mi][ni][j] = 0.f;

    const int a_row_l = (lane & 15);
    const int a_col_l = (lane & 16) ? 16 : 0;
    const int b_row_l = (lane & 7) + ((lane & 16) ? 8 : 0);
    const int b_col_l = (lane & 8) ? 16 : 0;

    const __half* Ap0 = g_xh + (size_t)m0 * DIN;
    const __half* Bp0 = g_wh + (size_t)n0 * DIN;

    auto issue_part = [&](int it, int slot, int part) {
        const int kc = it << 6;
        const int row = ld_row + part * 32;
        const uint32_t off = SMEM_SWIZZLE_128B((uint32_t)(row * 128 + ld_c * 16));
        const uint32_t sAb = smem_base + (uint32_t)slot * STAGE_BYTES;
        cp_async16(sAb + off,         Ap0 + kc + (size_t)row * DIN + ld_c * 8);
        cp_async16(sAb + 16384 + off, Bp0 + kc + (size_t)row * DIN + ld_c * 8);
    };
    auto issue_full = [&](int it, int slot) {
        #pragma unroll
        for (int p = 0; p < 4; ++p) issue_part(it, slot, p);
        cp_commit();
    };

    issue_full(0, 0);
    issue_full(1, 1);

    int slot = 0;        // slot of iter 'it'
    for (int it = 0; it < ITERS; ++it) {
        if (it + 1 < ITERS) cp_wait<1>();   // oldest (stage it) complete
        else                cp_wait<0>();
        __syncthreads();                    // compute(it-1) done; its slot is free

        const bool do_issue = (it + 2 < ITERS);
        int ns = slot + 2; if (ns >= NSTAGE) ns -= NSTAGE;

        const uint32_t sAb = smem_base + (uint32_t)slot * STAGE_BYTES;
        const uint32_t sBb = sAb + 16384;

        #pragma unroll
        for (int ks = 0; ks < 4; ++ks) {
            if (do_issue) issue_part(it + 2, ns, ks);   // spread STS across ks
            uint32_t a[4][4];
            uint32_t b[2][4];
            #pragma unroll
            for (int mi = 0; mi < 4; ++mi) {
                const int row = wm * 64 + mi * 16 + a_row_l;
                const int col = ks * 32 + a_col_l;
                const uint32_t addr = sAb + SMEM_SWIZZLE_128B((uint32_t)(row * 128 + col));
                ldm_x4(a[mi][0], a[mi][1], a[mi][2], a[mi][3], addr);
            }
            #pragma unroll
            for (int np = 0; np < 2; ++np) {
                const int row = wn * 32 + np * 16 + b_row_l;
                const int col = ks * 32 + b_col_l;
                const uint32_t addr = sBb + SMEM_SWIZZLE_128B((uint32_t)(row * 128 + col));
                ldm_x4(b[np][0], b[np][1], b[np][2], b[np][3], addr);
            }
            #pragma unroll
            for (int mi = 0; mi < 4; ++mi)
                #pragma unroll
                for (int ni = 0; ni < 4; ++ni) {
                    const uint32_t b0 = b[ni >> 1][(ni & 1) * 2];
                    const uint32_t b1 = b[ni >> 1][(ni & 1) * 2 + 1];
                    mma_f16(acc[mi][ni][0], acc[mi][ni][1], acc[mi][ni][2], acc[mi][ni][3],
                            a[mi][0], a[mi][1], a[mi][2], a[mi][3], b0, b1);
                }
        }
        if (do_issue) cp_commit();
        if (++slot >= NSTAGE) slot = 0;
    }

    // Epilogue: direct stores, float2 per fragment row, +bias.
    #pragma unroll
    for (int ni = 0; ni < 4; ++ni) {
        const int n = n0 + wn * 32 + ni * 8 + (lane & 3) * 2;
        const float bv0 = bias[n];
        const float bv1 = bias[n + 1];
        #pragma unroll
        for (int mi = 0; mi < 4; ++mi) {
            const int m = m0 + wm * 64 + mi * 16 + (lane >> 2);
            float2 v0 = make_float2(acc[mi][ni][0] + bv0, acc[mi][ni][1] + bv1);
            float2 v1 = make_float2(acc[mi][ni][2] + bv0, acc[mi][ni][3] + bv1);
            *(float2*)(out + (size_t)m * DOUT + n)       = v0;
            *(float2*)(out + (size_t)(m + 8) * DOUT + n) = v1;
        }
    }
}

// ============================================================================
// launch — single stream, 6 nodes.
// ============================================================================
extern "C" void kernel_launch(void* const* d_in, const int* in_sizes, int n_in,
                              void* d_out, int out_size) {
    const float* x      = (const float*)d_in[0];
    const float* W_base = (const float*)d_in[1];
    const float* b_base = (const float*)d_in[2];
    const float* enc0   = (const float*)d_in[3];
    const float* enc1   = (const float*)d_in[4];
    const float* coefs0 = (const float*)d_in[5];
    const float* coefs1 = (const float*)d_in[6];
    const void*  mask0  = d_in[7];
    const void*  mask1  = d_in[8];
    float* out = (float*)d_out;

    static int smem_set = 0;
    if (!smem_set) {
        cudaFuncSetAttribute(k_gemm, cudaFuncAttributeMaxDynamicSharedMemorySize, GEMM_SMEM);
        smem_set = 1;
    }

    // 0) detect mask dtype (g_viol statically zeroed; ORs are idempotent)
    k_detect<<<(NEXP * DOUT * R0 / 4) / 256, 256>>>((const unsigned int*)mask0);
    // 1) fused: masked coefficient sums + DC/Nyquist init of g_fw
    k_prep<<<(2 * DOUT * RTOT + 255) / 256, 256>>>(coefs0, coefs1, mask0, mask1);
    // 2) Fourier transform of the 40 coefficient columns along O
    k_transform<<<dim3(32, 16), 128>>>();
    // 3) fold rank-40 update via tensor-core K=40 GEMM (batched MLP~32 fills)
    k_build_w_mma<<<dim3(32, 32), 256>>>(W_base, enc0, enc1);
    // 4) convert activations to fp16
    k_cvt_x<<<(MROWS * DIN / 4) / 256, 256>>>(x);
    // 5) single-pass fp16 GEMM (R12 config)
    k_gemm<<<dim3(32, 64), 256, GEMM_SMEM>>>(b_base, out);
}